// round 3
// baseline (speedup 1.0000x reference)
#include <cuda_runtime.h>
#include <cuda_bf16.h>
#include <stdint.h>

// ---------------- problem constants (shapes fixed by the dataset) -----------
#define MAXN 100000
#define MAXE 1600000
#define IN_C 128
#define HID_C 128
#define OUT_C 64

// ---------------- device scratch (no allocs allowed; referenced directly) ---
__device__ __align__(16) float g_deg [MAXN];
__device__ __align__(16) float g_dinv[MAXN];
__device__ __align__(16) float g_norm[MAXE];
__device__ __align__(16) float g_h1[(size_t)MAXN * HID_C];
__device__ __align__(16) float g_a1[(size_t)MAXN * HID_C];
__device__ __align__(16) float g_h2[(size_t)MAXN * OUT_C];
__device__ __align__(16) float g_z [(size_t)MAXN * OUT_C];

// ---------------- normalization precompute ----------------------------------
__global__ void deg_init_kernel(int n) {
    int i = blockIdx.x * blockDim.x + threadIdx.x;
    if (i < n) g_deg[i] = 1.0f;   // self-loop weight
}

__global__ void deg_acc_kernel(const int* __restrict__ dst,
                               const float* __restrict__ ew, int ne) {
    int e = blockIdx.x * blockDim.x + threadIdx.x;
    if (e < ne) atomicAdd(&g_deg[dst[e]], ew[e]);
}

__global__ void dinv_kernel(int n) {
    int i = blockIdx.x * blockDim.x + threadIdx.x;
    if (i < n) {
        float d = g_deg[i];
        g_dinv[i] = (d > 0.0f) ? rsqrtf(d) : 0.0f;
    }
}

__global__ void norm_kernel(const int* __restrict__ src,
                            const int* __restrict__ dst,
                            const float* __restrict__ ew, int ne) {
    int e = blockIdx.x * blockDim.x + threadIdx.x;
    if (e < ne) g_norm[e] = g_dinv[src[e]] * ew[e] * g_dinv[dst[e]];
}

// ---------------- tiled FP32 GEMM: C[nrows, NOUT] = A[nrows,128] @ W[128,NOUT]
// LAYER 1: A = X (arg),  C = g_h1.   LAYER 2: A = g_a1, C = g_h2.
template<int NOUT, int LAYER>
__global__ void gemm_kernel(const float* __restrict__ X,
                            const float* __restrict__ W, int nrows) {
    const float* __restrict__ A = (LAYER == 1) ? X : (const float*)g_a1;
    float* __restrict__ C = (LAYER == 1) ? g_h1 : g_h2;

    constexpr int CPT = NOUT / 16;           // cols per thread (8 or 4)
    __shared__ float As[64][33];
    __shared__ float Ws[32 * NOUT];

    int tid = threadIdx.x;
    int tx = tid & 15, ty = tid >> 4;        // 16 x 16
    int row0 = blockIdx.x * 64;

    float acc[4][CPT];
#pragma unroll
    for (int i = 0; i < 4; i++)
#pragma unroll
        for (int j = 0; j < CPT; j++) acc[i][j] = 0.0f;

    for (int k0 = 0; k0 < 128; k0 += 32) {
        // A tile: 64 rows x 32 cols = 512 float4 lanes, 2 per thread
#pragma unroll
        for (int i = 0; i < 2; i++) {
            int idx = tid + i * 256;         // 0..511
            int r  = idx >> 3;
            int cs = (idx & 7) * 4;
            float4 v = make_float4(0.f, 0.f, 0.f, 0.f);
            int row = row0 + r;
            if (row < nrows) v = *(const float4*)(A + (size_t)row * 128 + k0 + cs);
            As[r][cs + 0] = v.x; As[r][cs + 1] = v.y;
            As[r][cs + 2] = v.z; As[r][cs + 3] = v.w;
        }
        // W tile: 32 full rows, contiguous 32*NOUT floats
        constexpr int WV = (32 * NOUT) / 4 / 256;
        const float4* Wg = (const float4*)(W + k0 * NOUT);
        float4* Wsv = (float4*)Ws;
#pragma unroll
        for (int i = 0; i < WV; i++) Wsv[tid + i * 256] = Wg[tid + i * 256];
        __syncthreads();

#pragma unroll
        for (int k = 0; k < 32; k++) {
            float a0 = As[ty * 4 + 0][k];
            float a1v = As[ty * 4 + 1][k];
            float a2 = As[ty * 4 + 2][k];
            float a3 = As[ty * 4 + 3][k];
            const float* wrow = &Ws[k * NOUT + tx * CPT];
#pragma unroll
            for (int j = 0; j < CPT; j++) {
                float b = wrow[j];
                acc[0][j] += a0 * b;
                acc[1][j] += a1v * b;
                acc[2][j] += a2 * b;
                acc[3][j] += a3 * b;
            }
        }
        __syncthreads();
    }

#pragma unroll
    for (int i = 0; i < 4; i++) {
        int row = row0 + ty * 4 + i;
        if (row < nrows) {
            float* cp = C + (size_t)row * NOUT + tx * CPT;
#pragma unroll
            for (int j = 0; j < CPT; j += 4)
                *(float4*)(cp + j) = make_float4(acc[i][j], acc[i][j + 1],
                                                 acc[i][j + 2], acc[i][j + 3]);
        }
    }
}

// ---------------- self-loop init: Out[i] = H[i] * dinv[i]^2 ------------------
template<int FEAT, int LAYER>
__global__ void selfloop_init_kernel(int nrows) {
    const float* __restrict__ H = (LAYER == 1) ? g_h1 : g_h2;
    float* __restrict__ Out = (LAYER == 1) ? g_a1 : g_z;
    constexpr int L = FEAT / 4;
    long long t = (long long)blockIdx.x * blockDim.x + threadIdx.x;
    if (t >= (long long)nrows * L) return;
    int node = (int)(t / L);
    float di = g_dinv[node];
    float s = di * di;
    float4 v = ((const float4*)H)[t];
    v.x *= s; v.y *= s; v.z *= s; v.w *= s;
    ((float4*)Out)[t] = v;
}

// ---------------- edge scatter: Out[dst] += H[src] * norm --------------------
template<int FEAT, int LAYER>
__global__ void scatter_kernel(const int* __restrict__ src,
                               const int* __restrict__ dst, int nedges) {
    const float* __restrict__ H = (LAYER == 1) ? g_h1 : g_h2;
    float* __restrict__ Out = (LAYER == 1) ? g_a1 : g_z;
    constexpr int L = FEAT / 4;
    long long t = (long long)blockIdx.x * blockDim.x + threadIdx.x;
    int e  = (int)(t / L);
    int li = (int)(t % L);
    if (e >= nedges) return;
    int s = src[e];
    int d = dst[e];
    float w = g_norm[e];
    float4 v = *(const float4*)(H + (size_t)s * FEAT + li * 4);
    float* p = Out + (size_t)d * FEAT + li * 4;
    unsigned long long gp = (unsigned long long)__cvta_generic_to_global((void*)p);
    asm volatile("red.global.add.v4.f32 [%0], {%1, %2, %3, %4};"
                 :: "l"(gp), "f"(v.x * w), "f"(v.y * w), "f"(v.z * w), "f"(v.w * w)
                 : "memory");
}

// ---------------- bias (+optional relu), in place ----------------------------
template<int FEAT, bool RELU, int LAYER>
__global__ void bias_act_kernel(const float* __restrict__ bias, int nrows) {
    float* __restrict__ A = (LAYER == 1) ? g_a1 : g_z;
    constexpr int L = FEAT / 4;
    long long t = (long long)blockIdx.x * blockDim.x + threadIdx.x;
    if (t >= (long long)nrows * L) return;
    int c4 = (int)(t % L);
    float4 v = ((float4*)A)[t];
    float4 b = ((const float4*)bias)[c4];
    v.x += b.x; v.y += b.y; v.z += b.z; v.w += b.w;
    if (RELU) {
        v.x = fmaxf(v.x, 0.0f); v.y = fmaxf(v.y, 0.0f);
        v.z = fmaxf(v.z, 0.0f); v.w = fmaxf(v.w, 0.0f);
    }
    ((float4*)A)[t] = v;
}

// ---------------- decode: out[e] = dot(z[a], z[b]) over 64 dims --------------
__global__ void decode_kernel(const int* __restrict__ ea,
                              const int* __restrict__ eb,
                              float* __restrict__ out, int ne) {
    long long t = (long long)blockIdx.x * blockDim.x + threadIdx.x;
    int e = (int)(t >> 5);
    int lane = (int)(t & 31);
    if (e >= ne) return;
    int a = ea[e];
    int b = eb[e];
    float2 va = *(const float2*)(g_z + (size_t)a * 64 + lane * 2);
    float2 vb = *(const float2*)(g_z + (size_t)b * 64 + lane * 2);
    float p = va.x * vb.x + va.y * vb.y;
#pragma unroll
    for (int o = 16; o > 0; o >>= 1) p += __shfl_down_sync(0xffffffffu, p, o);
    if (lane == 0) out[e] = p;
}

// ---------------- host launch ------------------------------------------------
static inline int cdiv_ll(long long a, int b) { return (int)((a + b - 1) / b); }

extern "C" void kernel_launch(void* const* d_in, const int* in_sizes, int n_in,
                              void* d_out, int out_size) {
    const float* x   = (const float*)d_in[0];
    const int*   ei  = (const int*)d_in[1];    // [2, E] int32
    const float* ew  = (const float*)d_in[2];
    const int*   eli = (const int*)d_in[3];    // [2, EL] int32
    const float* W1  = (const float*)d_in[4];
    const float* b1  = (const float*)d_in[5];
    const float* W2  = (const float*)d_in[6];
    const float* b2  = (const float*)d_in[7];
    float*       out = (float*)d_out;

    const int N  = in_sizes[0] / IN_C;
    const int E  = in_sizes[1] / 2;
    const int EL = in_sizes[3] / 2;

    const int* src = ei;
    const int* dst = ei + E;
    const int* ea  = eli;
    const int* eb  = eli + EL;

    const int T = 256;

    // normalization coefficients
    deg_init_kernel<<<cdiv_ll(N, T), T>>>(N);
    deg_acc_kernel<<<cdiv_ll(E, T), T>>>(dst, ew, E);
    dinv_kernel<<<cdiv_ll(N, T), T>>>(N);
    norm_kernel<<<cdiv_ll(E, T), T>>>(src, dst, ew, E);

    // layer 1: h1 = x @ W1 ; a1 = Agg(h1) ; a1 = relu(a1 + b1)
    gemm_kernel<HID_C, 1><<<cdiv_ll(N, 64), 256>>>(x, W1, N);
    selfloop_init_kernel<HID_C, 1><<<cdiv_ll((long long)N * (HID_C / 4), T), T>>>(N);
    scatter_kernel<HID_C, 1><<<cdiv_ll((long long)E * (HID_C / 4), T), T>>>(src, dst, E);
    bias_act_kernel<HID_C, true, 1><<<cdiv_ll((long long)N * (HID_C / 4), T), T>>>(b1, N);

    // layer 2: h2 = a1 @ W2 ; z = Agg(h2) ; z = z + b2
    gemm_kernel<OUT_C, 2><<<cdiv_ll(N, 64), 256>>>(x, W2, N);
    selfloop_init_kernel<OUT_C, 2><<<cdiv_ll((long long)N * (OUT_C / 4), T), T>>>(N);
    scatter_kernel<OUT_C, 2><<<cdiv_ll((long long)E * (OUT_C / 4), T), T>>>(src, dst, E);
    bias_act_kernel<OUT_C, false, 2><<<cdiv_ll((long long)N * (OUT_C / 4), T), T>>>(b2, N);

    // decode
    decode_kernel<<<cdiv_ll((long long)EL * 32, T), T>>>(ea, eb, out, EL);
}

// round 4
// speedup vs baseline: 1.0479x; 1.0479x over previous
#include <cuda_runtime.h>
#include <cuda_bf16.h>
#include <stdint.h>

// ---------------- problem constants (shapes fixed by the dataset) -----------
#define MAXN 100000
#define MAXE 1600000
#define IN_C 128
#define HID_C 128
#define OUT_C 64

// ---------------- device scratch (no allocs allowed; referenced directly) ---
__device__ __align__(16) float g_deg [MAXN];
__device__ __align__(16) float g_dinv[MAXN];
__device__ __align__(16) float g_norm[MAXE];
__device__ __align__(16) float g_h1[(size_t)MAXN * HID_C];
__device__ __align__(16) float g_a1[(size_t)MAXN * HID_C];
__device__ __align__(16) float g_h2[(size_t)MAXN * OUT_C];
__device__ __align__(16) float g_z [(size_t)MAXN * OUT_C];

// ---------------- normalization precompute ----------------------------------
__global__ void deg_init_kernel(int n) {
    int i = blockIdx.x * blockDim.x + threadIdx.x;
    if (i < n) g_deg[i] = 1.0f;   // self-loop weight
}

__global__ void deg_acc_kernel(const int* __restrict__ dst,
                               const float* __restrict__ ew, int ne) {
    int e = blockIdx.x * blockDim.x + threadIdx.x;
    if (e < ne) atomicAdd(&g_deg[dst[e]], ew[e]);
}

__global__ void dinv_kernel(int n) {
    int i = blockIdx.x * blockDim.x + threadIdx.x;
    if (i < n) {
        float d = g_deg[i];
        g_dinv[i] = (d > 0.0f) ? rsqrtf(d) : 0.0f;
    }
}

__global__ void norm_kernel(const int* __restrict__ src,
                            const int* __restrict__ dst,
                            const float* __restrict__ ew, int ne) {
    int e = blockIdx.x * blockDim.x + threadIdx.x;
    if (e < ne) g_norm[e] = g_dinv[src[e]] * ew[e] * g_dinv[dst[e]];
}

// ---------------- tiled FP32 GEMM with fused epilogue ------------------------
// C[nrows, NOUT] = A[nrows,128] @ W[128,NOUT]; also Out[row] = C[row]*dinv[row]^2
// LAYER 1: A = X (arg),           C = g_h1, Out = g_a1
// LAYER 2: A = relu(g_a1 + b1),   C = g_h2, Out = g_z
template<int NOUT, int LAYER>
__global__ void gemm_kernel(const float* __restrict__ X,
                            const float* __restrict__ W,
                            const float* __restrict__ bias_in,  // b1 for LAYER 2
                            int nrows) {
    const float* __restrict__ A = (LAYER == 1) ? X : (const float*)g_a1;
    float* __restrict__ C   = (LAYER == 1) ? g_h1 : g_h2;
    float* __restrict__ Out = (LAYER == 1) ? g_a1 : g_z;

    constexpr int CPT = NOUT / 16;           // cols per thread (8 or 4)
    __shared__ float As[64][33];
    __shared__ float Ws[32 * NOUT];

    int tid = threadIdx.x;
    int tx = tid & 15, ty = tid >> 4;        // 16 x 16
    int row0 = blockIdx.x * 64;

    float acc[4][CPT];
#pragma unroll
    for (int i = 0; i < 4; i++)
#pragma unroll
        for (int j = 0; j < CPT; j++) acc[i][j] = 0.0f;

    for (int k0 = 0; k0 < 128; k0 += 32) {
        // A tile: 64 rows x 32 cols = 512 float4 lanes, 2 per thread
#pragma unroll
        for (int i = 0; i < 2; i++) {
            int idx = tid + i * 256;         // 0..511
            int r  = idx >> 3;
            int cs = (idx & 7) * 4;
            float4 v = make_float4(0.f, 0.f, 0.f, 0.f);
            int row = row0 + r;
            if (row < nrows) {
                v = *(const float4*)(A + (size_t)row * 128 + k0 + cs);
                if (LAYER == 2) {
                    float4 b = *(const float4*)(bias_in + k0 + cs);
                    v.x = fmaxf(v.x + b.x, 0.0f);
                    v.y = fmaxf(v.y + b.y, 0.0f);
                    v.z = fmaxf(v.z + b.z, 0.0f);
                    v.w = fmaxf(v.w + b.w, 0.0f);
                }
            }
            As[r][cs + 0] = v.x; As[r][cs + 1] = v.y;
            As[r][cs + 2] = v.z; As[r][cs + 3] = v.w;
        }
        // W tile: 32 full rows, contiguous 32*NOUT floats
        constexpr int WV = (32 * NOUT) / 4 / 256;
        const float4* Wg = (const float4*)(W + k0 * NOUT);
        float4* Wsv = (float4*)Ws;
#pragma unroll
        for (int i = 0; i < WV; i++) Wsv[tid + i * 256] = Wg[tid + i * 256];
        __syncthreads();

#pragma unroll
        for (int k = 0; k < 32; k++) {
            float a0 = As[ty * 4 + 0][k];
            float a1v = As[ty * 4 + 1][k];
            float a2 = As[ty * 4 + 2][k];
            float a3 = As[ty * 4 + 3][k];
            const float* wrow = &Ws[k * NOUT + tx * CPT];
#pragma unroll
            for (int j = 0; j < CPT; j++) {
                float b = wrow[j];
                acc[0][j] += a0 * b;
                acc[1][j] += a1v * b;
                acc[2][j] += a2 * b;
                acc[3][j] += a3 * b;
            }
        }
        __syncthreads();
    }

    // epilogue: write h and out = h * dinv[row]^2
#pragma unroll
    for (int i = 0; i < 4; i++) {
        int row = row0 + ty * 4 + i;
        if (row < nrows) {
            float di = g_dinv[row];
            float s = di * di;
            float* cp = C   + (size_t)row * NOUT + tx * CPT;
            float* op = Out + (size_t)row * NOUT + tx * CPT;
#pragma unroll
            for (int j = 0; j < CPT; j += 4) {
                float4 h = make_float4(acc[i][j], acc[i][j + 1],
                                       acc[i][j + 2], acc[i][j + 3]);
                *(float4*)(cp + j) = h;
                *(float4*)(op + j) = make_float4(h.x * s, h.y * s, h.z * s, h.w * s);
            }
        }
    }
}

// ---------------- edge scatter: Out[dst] += H[src] * norm --------------------
template<int FEAT, int LAYER>
__global__ void scatter_kernel(const int* __restrict__ src,
                               const int* __restrict__ dst, int nedges) {
    const float* __restrict__ H = (LAYER == 1) ? g_h1 : g_h2;
    float* __restrict__ Out = (LAYER == 1) ? g_a1 : g_z;
    constexpr int L = FEAT / 4;
    long long t = (long long)blockIdx.x * blockDim.x + threadIdx.x;
    int e  = (int)(t / L);
    int li = (int)(t % L);
    if (e >= nedges) return;
    int s = src[e];
    int d = dst[e];
    float w = g_norm[e];
    float4 v = *(const float4*)(H + (size_t)s * FEAT + li * 4);
    float* p = Out + (size_t)d * FEAT + li * 4;
    unsigned long long gp = (unsigned long long)__cvta_generic_to_global((void*)p);
    asm volatile("red.global.add.v4.f32 [%0], {%1, %2, %3, %4};"
                 :: "l"(gp), "f"(v.x * w), "f"(v.y * w), "f"(v.z * w), "f"(v.w * w)
                 : "memory");
}

// ---------------- decode: out[e] = dot(z[a]+b2, z[b]+b2) over 64 dims --------
__global__ void decode_kernel(const int* __restrict__ ea,
                              const int* __restrict__ eb,
                              const float* __restrict__ b2,
                              float* __restrict__ out, int ne) {
    long long t = (long long)blockIdx.x * blockDim.x + threadIdx.x;
    int e = (int)(t >> 5);
    int lane = (int)(t & 31);
    if (e >= ne) return;
    int a = ea[e];
    int b = eb[e];
    float2 bb = *(const float2*)(b2 + lane * 2);
    float2 va = *(const float2*)(g_z + (size_t)a * 64 + lane * 2);
    float2 vb = *(const float2*)(g_z + (size_t)b * 64 + lane * 2);
    va.x += bb.x; va.y += bb.y;
    vb.x += bb.x; vb.y += bb.y;
    float p = va.x * vb.x + va.y * vb.y;
#pragma unroll
    for (int o = 16; o > 0; o >>= 1) p += __shfl_down_sync(0xffffffffu, p, o);
    if (lane == 0) out[e] = p;
}

// ---------------- host launch ------------------------------------------------
static inline int cdiv_ll(long long a, int b) { return (int)((a + b - 1) / b); }

extern "C" void kernel_launch(void* const* d_in, const int* in_sizes, int n_in,
                              void* d_out, int out_size) {
    const float* x   = (const float*)d_in[0];
    const int*   ei  = (const int*)d_in[1];    // [2, E] int32
    const float* ew  = (const float*)d_in[2];
    const int*   eli = (const int*)d_in[3];    // [2, EL] int32
    const float* W1  = (const float*)d_in[4];
    const float* b1  = (const float*)d_in[5];
    const float* W2  = (const float*)d_in[6];
    const float* b2  = (const float*)d_in[7];
    float*       out = (float*)d_out;

    const int N  = in_sizes[0] / IN_C;
    const int E  = in_sizes[1] / 2;
    const int EL = in_sizes[3] / 2;

    const int* src = ei;
    const int* dst = ei + E;
    const int* ea  = eli;
    const int* eb  = eli + EL;

    const int T = 256;

    // normalization coefficients
    deg_init_kernel<<<cdiv_ll(N, T), T>>>(N);
    deg_acc_kernel<<<cdiv_ll(E, T), T>>>(dst, ew, E);
    dinv_kernel<<<cdiv_ll(N, T), T>>>(N);
    norm_kernel<<<cdiv_ll(E, T), T>>>(src, dst, ew, E);

    // layer 1: h1 = x @ W1 ; a1 = h1*dinv^2 (fused) ; a1 += scatter(h1)
    gemm_kernel<HID_C, 1><<<cdiv_ll(N, 64), 256>>>(x, W1, nullptr, N);
    scatter_kernel<HID_C, 1><<<cdiv_ll((long long)E * (HID_C / 4), T), T>>>(src, dst, E);

    // layer 2: h2 = relu(a1+b1) @ W2 (bias+relu fused in A-load) ;
    //          z = h2*dinv^2 (fused) ; z += scatter(h2)
    gemm_kernel<OUT_C, 2><<<cdiv_ll(N, 64), 256>>>(x, W2, b1, N);
    scatter_kernel<OUT_C, 2><<<cdiv_ll((long long)E * (OUT_C / 4), T), T>>>(src, dst, E);

    // decode (b2 fused)
    decode_kernel<<<cdiv_ll((long long)EL * 32, T), T>>>(ea, eb, b2, out, EL);
}

// round 5
// speedup vs baseline: 1.0685x; 1.0196x over previous
#include <cuda_runtime.h>
#include <cuda_bf16.h>
#include <stdint.h>

// ---------------- problem constants (shapes fixed by the dataset) -----------
#define MAXN 100000
#define MAXE 1600000
#define IN_C 128
#define HID_C 128
#define OUT_C 64
#define SCAN_T 1024

// ---------------- device scratch (no allocs; referenced directly) -----------
__device__ __align__(16) float g_deg [MAXN];
__device__ __align__(16) float g_dinv[MAXN];
__device__ __align__(16) int   g_cnt [MAXN];
__device__ __align__(16) int   g_cur [MAXN];
__device__ __align__(16) int   g_off [MAXN + 1];
__device__ __align__(16) int   g_csr_src[MAXE];
__device__ __align__(16) float g_csr_w  [MAXE];
__device__ __align__(16) float g_h1[(size_t)MAXN * HID_C];
__device__ __align__(16) float g_a1[(size_t)MAXN * HID_C];
__device__ __align__(16) float g_h2[(size_t)MAXN * OUT_C];
__device__ __align__(16) float g_z [(size_t)MAXN * OUT_C];

// ---------------- degree + in-edge counting ---------------------------------
__global__ void init_kernel(int n) {
    int i = blockIdx.x * blockDim.x + threadIdx.x;
    if (i < n) { g_deg[i] = 1.0f; g_cnt[i] = 0; }   // self-loop weight, zero counts
}

__global__ void deg_cnt_kernel(const int* __restrict__ dst,
                               const float* __restrict__ ew, int ne) {
    int e = blockIdx.x * blockDim.x + threadIdx.x;
    if (e < ne) {
        int d = dst[e];
        atomicAdd(&g_deg[d], ew[e]);
        atomicAdd(&g_cnt[d], 1);
    }
}

__global__ void dinv_kernel(int n) {
    int i = blockIdx.x * blockDim.x + threadIdx.x;
    if (i < n) {
        float d = g_deg[i];
        g_dinv[i] = (d > 0.0f) ? rsqrtf(d) : 0.0f;
    }
}

// single-block exclusive scan of g_cnt -> g_off (and g_cur copy)
__global__ void scan_kernel(int n) {
    __shared__ int ssum[SCAN_T];
    int tid = threadIdx.x;
    int chunk = (n + SCAN_T - 1) / SCAN_T;
    int b = tid * chunk;
    int e = min(b + chunk, n);
    int s = 0;
    for (int i = b; i < e; i++) s += g_cnt[i];
    ssum[tid] = s;
    __syncthreads();
    for (int off = 1; off < SCAN_T; off <<= 1) {
        int v = 0;
        if (tid >= off) v = ssum[tid - off];
        __syncthreads();
        if (tid >= off) ssum[tid] += v;
        __syncthreads();
    }
    int run = ssum[tid] - s;   // exclusive prefix of this thread's chunk
    for (int i = b; i < e; i++) {
        int c = g_cnt[i];
        g_off[i] = run;
        g_cur[i] = run;
        run += c;
    }
    if (tid == SCAN_T - 1) g_off[n] = run;
}

// fill CSR: (src, w) pairs grouped by dst
__global__ void fill_kernel(const int* __restrict__ src,
                            const int* __restrict__ dst,
                            const float* __restrict__ ew, int ne) {
    int e = blockIdx.x * blockDim.x + threadIdx.x;
    if (e >= ne) return;
    int s = src[e];
    int d = dst[e];
    int slot = atomicAdd(&g_cur[d], 1);
    g_csr_src[slot] = s;
    g_csr_w[slot]   = g_dinv[s] * ew[e] * g_dinv[d];
}

// ---------------- tiled FP32 GEMM -------------------------------------------
// C[nrows, NOUT] = A[nrows,128] @ W[128,NOUT]
// LAYER 1: A = X (arg),         C = g_h1
// LAYER 2: A = relu(g_a1 + b1), C = g_h2
template<int NOUT, int LAYER>
__global__ void gemm_kernel(const float* __restrict__ X,
                            const float* __restrict__ W,
                            const float* __restrict__ bias_in,
                            int nrows) {
    const float* __restrict__ A = (LAYER == 1) ? X : (const float*)g_a1;
    float* __restrict__ C = (LAYER == 1) ? g_h1 : g_h2;

    constexpr int CPT = NOUT / 16;           // cols per thread (8 or 4)
    __shared__ float As[64][33];
    __shared__ float Ws[32 * NOUT];

    int tid = threadIdx.x;
    int tx = tid & 15, ty = tid >> 4;        // 16 x 16
    int row0 = blockIdx.x * 64;

    float acc[4][CPT];
#pragma unroll
    for (int i = 0; i < 4; i++)
#pragma unroll
        for (int j = 0; j < CPT; j++) acc[i][j] = 0.0f;

    for (int k0 = 0; k0 < 128; k0 += 32) {
#pragma unroll
        for (int i = 0; i < 2; i++) {
            int idx = tid + i * 256;         // 0..511
            int r  = idx >> 3;
            int cs = (idx & 7) * 4;
            float4 v = make_float4(0.f, 0.f, 0.f, 0.f);
            int row = row0 + r;
            if (row < nrows) {
                v = *(const float4*)(A + (size_t)row * 128 + k0 + cs);
                if (LAYER == 2) {
                    float4 b = *(const float4*)(bias_in + k0 + cs);
                    v.x = fmaxf(v.x + b.x, 0.0f);
                    v.y = fmaxf(v.y + b.y, 0.0f);
                    v.z = fmaxf(v.z + b.z, 0.0f);
                    v.w = fmaxf(v.w + b.w, 0.0f);
                }
            }
            As[r][cs + 0] = v.x; As[r][cs + 1] = v.y;
            As[r][cs + 2] = v.z; As[r][cs + 3] = v.w;
        }
        constexpr int WV = (32 * NOUT) / 4 / 256;
        const float4* Wg = (const float4*)(W + k0 * NOUT);
        float4* Wsv = (float4*)Ws;
#pragma unroll
        for (int i = 0; i < WV; i++) Wsv[tid + i * 256] = Wg[tid + i * 256];
        __syncthreads();

#pragma unroll
        for (int k = 0; k < 32; k++) {
            float a0 = As[ty * 4 + 0][k];
            float a1v = As[ty * 4 + 1][k];
            float a2 = As[ty * 4 + 2][k];
            float a3 = As[ty * 4 + 3][k];
            const float* wrow = &Ws[k * NOUT + tx * CPT];
#pragma unroll
            for (int j = 0; j < CPT; j++) {
                float b = wrow[j];
                acc[0][j] += a0 * b;
                acc[1][j] += a1v * b;
                acc[2][j] += a2 * b;
                acc[3][j] += a3 * b;
            }
        }
        __syncthreads();
    }

#pragma unroll
    for (int i = 0; i < 4; i++) {
        int row = row0 + ty * 4 + i;
        if (row < nrows) {
            float* cp = C + (size_t)row * NOUT + tx * CPT;
#pragma unroll
            for (int j = 0; j < CPT; j += 4)
                *(float4*)(cp + j) = make_float4(acc[i][j], acc[i][j + 1],
                                                 acc[i][j + 2], acc[i][j + 3]);
        }
    }
}

// ---------------- CSR gather aggregation: warp per dst node ------------------
// Out[n] = H[n]*dinv[n]^2 + sum_{edges e: dst=n} w_e * H[src_e]
template<int FEAT, int LAYER>
__global__ void gather_kernel(int n) {
    const float* __restrict__ H = (LAYER == 1) ? g_h1 : g_h2;
    float* __restrict__ Out = (LAYER == 1) ? g_a1 : g_z;
    constexpr int VW = FEAT / 32;            // floats per lane (4 or 2)

    int t = blockIdx.x * blockDim.x + threadIdx.x;
    int node = t >> 5;
    int lane = t & 31;
    if (node >= n) return;

    float di = g_dinv[node];
    float sc = di * di;

    float acc[VW];
    {
        const float* hp = H + (size_t)node * FEAT + lane * VW;
        if constexpr (VW == 4) {
            float4 f = *(const float4*)hp;
            acc[0] = f.x * sc; acc[1] = f.y * sc; acc[2] = f.z * sc; acc[3] = f.w * sc;
        } else {
            float2 f = *(const float2*)hp;
            acc[0] = f.x * sc; acc[1] = f.y * sc;
        }
    }

    int i   = g_off[node];
    int end = g_off[node + 1];

    for (; i + 2 <= end; i += 2) {
        int   s0 = g_csr_src[i];
        int   s1 = g_csr_src[i + 1];
        float w0 = g_csr_w[i];
        float w1 = g_csr_w[i + 1];
        const float* p0 = H + (size_t)s0 * FEAT + lane * VW;
        const float* p1 = H + (size_t)s1 * FEAT + lane * VW;
        if constexpr (VW == 4) {
            float4 v0 = *(const float4*)p0;
            float4 v1 = *(const float4*)p1;
            acc[0] += v0.x * w0 + v1.x * w1;
            acc[1] += v0.y * w0 + v1.y * w1;
            acc[2] += v0.z * w0 + v1.z * w1;
            acc[3] += v0.w * w0 + v1.w * w1;
        } else {
            float2 v0 = *(const float2*)p0;
            float2 v1 = *(const float2*)p1;
            acc[0] += v0.x * w0 + v1.x * w1;
            acc[1] += v0.y * w0 + v1.y * w1;
        }
    }
    if (i < end) {
        int   s0 = g_csr_src[i];
        float w0 = g_csr_w[i];
        const float* p0 = H + (size_t)s0 * FEAT + lane * VW;
        if constexpr (VW == 4) {
            float4 v0 = *(const float4*)p0;
            acc[0] += v0.x * w0; acc[1] += v0.y * w0;
            acc[2] += v0.z * w0; acc[3] += v0.w * w0;
        } else {
            float2 v0 = *(const float2*)p0;
            acc[0] += v0.x * w0; acc[1] += v0.y * w0;
        }
    }

    float* op = Out + (size_t)node * FEAT + lane * VW;
    if constexpr (VW == 4)
        *(float4*)op = make_float4(acc[0], acc[1], acc[2], acc[3]);
    else
        *(float2*)op = make_float2(acc[0], acc[1]);
}

// ---------------- decode: out[e] = dot(z[a]+b2, z[b]+b2) over 64 dims --------
__global__ void decode_kernel(const int* __restrict__ ea,
                              const int* __restrict__ eb,
                              const float* __restrict__ b2,
                              float* __restrict__ out, int ne) {
    long long t = (long long)blockIdx.x * blockDim.x + threadIdx.x;
    int e = (int)(t >> 5);
    int lane = (int)(t & 31);
    if (e >= ne) return;
    int a = ea[e];
    int b = eb[e];
    float2 bb = *(const float2*)(b2 + lane * 2);
    float2 va = *(const float2*)(g_z + (size_t)a * 64 + lane * 2);
    float2 vb = *(const float2*)(g_z + (size_t)b * 64 + lane * 2);
    va.x += bb.x; va.y += bb.y;
    vb.x += bb.x; vb.y += bb.y;
    float p = va.x * vb.x + va.y * vb.y;
#pragma unroll
    for (int o = 16; o > 0; o >>= 1) p += __shfl_down_sync(0xffffffffu, p, o);
    if (lane == 0) out[e] = p;
}

// ---------------- host launch ------------------------------------------------
static inline int cdiv_ll(long long a, int b) { return (int)((a + b - 1) / b); }

extern "C" void kernel_launch(void* const* d_in, const int* in_sizes, int n_in,
                              void* d_out, int out_size) {
    const float* x   = (const float*)d_in[0];
    const int*   ei  = (const int*)d_in[1];    // [2, E] int32
    const float* ew  = (const float*)d_in[2];
    const int*   eli = (const int*)d_in[3];    // [2, EL] int32
    const float* W1  = (const float*)d_in[4];
    const float* b1  = (const float*)d_in[5];
    const float* W2  = (const float*)d_in[6];
    const float* b2  = (const float*)d_in[7];
    float*       out = (float*)d_out;

    const int N  = in_sizes[0] / IN_C;
    const int E  = in_sizes[1] / 2;
    const int EL = in_sizes[3] / 2;

    const int* src = ei;
    const int* dst = ei + E;
    const int* ea  = eli;
    const int* eb  = eli + EL;

    const int T = 256;

    // CSR build + normalization
    init_kernel<<<cdiv_ll(N, T), T>>>(N);
    deg_cnt_kernel<<<cdiv_ll(E, T), T>>>(dst, ew, E);
    dinv_kernel<<<cdiv_ll(N, T), T>>>(N);
    scan_kernel<<<1, SCAN_T>>>(N);
    fill_kernel<<<cdiv_ll(E, T), T>>>(src, dst, ew, E);

    // layer 1: h1 = x @ W1 ; a1 = gather(h1)
    gemm_kernel<HID_C, 1><<<cdiv_ll(N, 64), 256>>>(x, W1, nullptr, N);
    gather_kernel<HID_C, 1><<<cdiv_ll((long long)N * 32, T), T>>>(N);

    // layer 2: h2 = relu(a1+b1) @ W2 ; z = gather(h2)
    gemm_kernel<OUT_C, 2><<<cdiv_ll(N, 64), 256>>>(x, W2, b1, N);
    gather_kernel<OUT_C, 2><<<cdiv_ll((long long)N * 32, T), T>>>(N);

    // decode (b2 fused)
    decode_kernel<<<cdiv_ll((long long)EL * 32, T), T>>>(ea, eb, b2, out, EL);
}

// round 6
// speedup vs baseline: 1.5348x; 1.4364x over previous
#include <cuda_runtime.h>
#include <cuda_bf16.h>
#include <stdint.h>

// ---------------- problem constants (shapes fixed by the dataset) -----------
#define MAXN 100000
#define MAXE 1600000
#define IN_C 128
#define HID_C 128
#define OUT_C 64
#define SCAN_BT 1024                       // threads per scan block
#define SCAN_NB ((MAXN + SCAN_BT - 1) / SCAN_BT)   // 98 blocks max

// ---------------- device scratch (no allocs; referenced directly) -----------
__device__ __align__(16) float g_deg [MAXN];
__device__ __align__(16) float g_dinv[MAXN];
__device__ __align__(16) int   g_cnt [MAXN];
__device__ __align__(16) int   g_cur [MAXN];
__device__ __align__(16) int   g_off [MAXN + 1];
__device__ __align__(16) int   g_bsum[128];
__device__ __align__(16) int   g_csr_src[MAXE];
__device__ __align__(16) float g_csr_w  [MAXE];
__device__ __align__(16) float g_h1[(size_t)MAXN * HID_C];
__device__ __align__(16) float g_a1[(size_t)MAXN * HID_C];
__device__ __align__(16) float g_h2[(size_t)MAXN * OUT_C];
__device__ __align__(16) float g_z [(size_t)MAXN * OUT_C];

// ---------------- degree + in-edge counting ---------------------------------
__global__ void init_kernel(int n) {
    int i = blockIdx.x * blockDim.x + threadIdx.x;
    if (i < n) { g_deg[i] = 1.0f; g_cnt[i] = 0; }   // self-loop weight, zero counts
}

__global__ void deg_cnt_kernel(const int* __restrict__ dst,
                               const float* __restrict__ ew, int ne) {
    int e = blockIdx.x * blockDim.x + threadIdx.x;
    if (e < ne) {
        int d = dst[e];
        atomicAdd(&g_deg[d], ew[e]);
        atomicAdd(&g_cnt[d], 1);
    }
}

__global__ void dinv_kernel(int n) {
    int i = blockIdx.x * blockDim.x + threadIdx.x;
    if (i < n) {
        float d = g_deg[i];
        g_dinv[i] = (d > 0.0f) ? rsqrtf(d) : 0.0f;
    }
}

// ---------------- two-level coalesced scan of g_cnt -> g_off ----------------
// pass 1: per-block sum
__global__ void scan1_kernel(int n) {
    __shared__ int wsum[32];
    int tid = threadIdx.x;
    int i = blockIdx.x * SCAN_BT + tid;
    int v = (i < n) ? g_cnt[i] : 0;
    // warp reduce
    int s = v;
#pragma unroll
    for (int o = 16; o > 0; o >>= 1) s += __shfl_down_sync(0xffffffffu, s, o);
    if ((tid & 31) == 0) wsum[tid >> 5] = s;
    __syncthreads();
    if (tid < 32) {
        int t = wsum[tid];
#pragma unroll
        for (int o = 16; o > 0; o >>= 1) t += __shfl_down_sync(0xffffffffu, t, o);
        if (tid == 0) g_bsum[blockIdx.x] = t;
    }
}

// pass 2: exclusive scan of block sums (nb <= 128), single block of 128
__global__ void scan2_kernel(int nb) {
    __shared__ int sh[128];
    int tid = threadIdx.x;
    int v = (tid < nb) ? g_bsum[tid] : 0;
    sh[tid] = v;
    __syncthreads();
#pragma unroll
    for (int o = 1; o < 128; o <<= 1) {
        int y = 0;
        if (tid >= o) y = sh[tid - o];
        __syncthreads();
        if (tid >= o) sh[tid] += y;
        __syncthreads();
    }
    if (tid < nb) g_bsum[tid] = sh[tid] - v;   // exclusive
}

// pass 3: per-block exclusive scan + block prefix -> g_off, g_cur
__global__ void scan3_kernel(int n) {
    __shared__ int wpre[32];
    int tid = threadIdx.x;
    int lane = tid & 31;
    int wid = tid >> 5;
    int i = blockIdx.x * SCAN_BT + tid;
    int v = (i < n) ? g_cnt[i] : 0;
    // inclusive warp scan
    int x = v;
#pragma unroll
    for (int o = 1; o < 32; o <<= 1) {
        int y = __shfl_up_sync(0xffffffffu, x, o);
        if (lane >= o) x += y;
    }
    if (lane == 31) wpre[wid] = x;
    __syncthreads();
    if (wid == 0) {
        int t = wpre[lane];
        int tv = t;
#pragma unroll
        for (int o = 1; o < 32; o <<= 1) {
            int y = __shfl_up_sync(0xffffffffu, tv, o);
            if (lane >= o) tv += y;
        }
        wpre[lane] = tv - t;   // exclusive warp prefix
    }
    __syncthreads();
    int bpre = g_bsum[blockIdx.x];
    int excl = bpre + wpre[wid] + (x - v);
    if (i < n) {
        g_off[i] = excl;
        g_cur[i] = excl;
        if (i == n - 1) g_off[n] = excl + v;
    }
}

// fill CSR: (src, w) pairs grouped by dst
__global__ void fill_kernel(const int* __restrict__ src,
                            const int* __restrict__ dst,
                            const float* __restrict__ ew, int ne) {
    int e = blockIdx.x * blockDim.x + threadIdx.x;
    if (e >= ne) return;
    int s = src[e];
    int d = dst[e];
    int slot = atomicAdd(&g_cur[d], 1);
    g_csr_src[slot] = s;
    g_csr_w[slot]   = g_dinv[s] * ew[e] * g_dinv[d];
}

// ---------------- tiled FP32 GEMM -------------------------------------------
// C[nrows, NOUT] = A[nrows,128] @ W[128,NOUT]
// LAYER 1: A = X (arg),         C = g_h1
// LAYER 2: A = relu(g_a1 + b1), C = g_h2
template<int NOUT, int LAYER>
__global__ void gemm_kernel(const float* __restrict__ X,
                            const float* __restrict__ W,
                            const float* __restrict__ bias_in,
                            int nrows) {
    const float* __restrict__ A = (LAYER == 1) ? X : (const float*)g_a1;
    float* __restrict__ C = (LAYER == 1) ? g_h1 : g_h2;

    constexpr int CPT = NOUT / 16;           // cols per thread (8 or 4)
    __shared__ float As[64][33];
    __shared__ float Ws[32 * NOUT];

    int tid = threadIdx.x;
    int tx = tid & 15, ty = tid >> 4;        // 16 x 16
    int row0 = blockIdx.x * 64;

    float acc[4][CPT];
#pragma unroll
    for (int i = 0; i < 4; i++)
#pragma unroll
        for (int j = 0; j < CPT; j++) acc[i][j] = 0.0f;

    for (int k0 = 0; k0 < 128; k0 += 32) {
#pragma unroll
        for (int i = 0; i < 2; i++) {
            int idx = tid + i * 256;         // 0..511
            int r  = idx >> 3;
            int cs = (idx & 7) * 4;
            float4 v = make_float4(0.f, 0.f, 0.f, 0.f);
            int row = row0 + r;
            if (row < nrows) {
                v = *(const float4*)(A + (size_t)row * 128 + k0 + cs);
                if (LAYER == 2) {
                    float4 b = *(const float4*)(bias_in + k0 + cs);
                    v.x = fmaxf(v.x + b.x, 0.0f);
                    v.y = fmaxf(v.y + b.y, 0.0f);
                    v.z = fmaxf(v.z + b.z, 0.0f);
                    v.w = fmaxf(v.w + b.w, 0.0f);
                }
            }
            As[r][cs + 0] = v.x; As[r][cs + 1] = v.y;
            As[r][cs + 2] = v.z; As[r][cs + 3] = v.w;
        }
        constexpr int WV = (32 * NOUT) / 4 / 256;
        const float4* Wg = (const float4*)(W + k0 * NOUT);
        float4* Wsv = (float4*)Ws;
#pragma unroll
        for (int i = 0; i < WV; i++) Wsv[tid + i * 256] = Wg[tid + i * 256];
        __syncthreads();

#pragma unroll
        for (int k = 0; k < 32; k++) {
            float a0 = As[ty * 4 + 0][k];
            float a1v = As[ty * 4 + 1][k];
            float a2 = As[ty * 4 + 2][k];
            float a3 = As[ty * 4 + 3][k];
            const float* wrow = &Ws[k * NOUT + tx * CPT];
#pragma unroll
            for (int j = 0; j < CPT; j++) {
                float b = wrow[j];
                acc[0][j] += a0 * b;
                acc[1][j] += a1v * b;
                acc[2][j] += a2 * b;
                acc[3][j] += a3 * b;
            }
        }
        __syncthreads();
    }

#pragma unroll
    for (int i = 0; i < 4; i++) {
        int row = row0 + ty * 4 + i;
        if (row < nrows) {
            float* cp = C + (size_t)row * NOUT + tx * CPT;
#pragma unroll
            for (int j = 0; j < CPT; j += 4)
                *(float4*)(cp + j) = make_float4(acc[i][j], acc[i][j + 1],
                                                 acc[i][j + 2], acc[i][j + 3]);
        }
    }
}

// ---------------- CSR gather aggregation: warp per dst node ------------------
// Out[n] = H[n]*dinv[n]^2 + sum_{edges e: dst=n} w_e * H[src_e]
template<int FEAT, int LAYER>
__global__ void gather_kernel(int n) {
    const float* __restrict__ H = (LAYER == 1) ? g_h1 : g_h2;
    float* __restrict__ Out = (LAYER == 1) ? g_a1 : g_z;
    constexpr int VW = FEAT / 32;            // floats per lane (4 or 2)

    int t = blockIdx.x * blockDim.x + threadIdx.x;
    int node = t >> 5;
    int lane = t & 31;
    if (node >= n) return;

    float di = g_dinv[node];
    float sc = di * di;

    float acc[VW];
    {
        const float* hp = H + (size_t)node * FEAT + lane * VW;
        if constexpr (VW == 4) {
            float4 f = *(const float4*)hp;
            acc[0] = f.x * sc; acc[1] = f.y * sc; acc[2] = f.z * sc; acc[3] = f.w * sc;
        } else {
            float2 f = *(const float2*)hp;
            acc[0] = f.x * sc; acc[1] = f.y * sc;
        }
    }

    int i   = g_off[node];
    int end = g_off[node + 1];

    for (; i + 2 <= end; i += 2) {
        int   s0 = g_csr_src[i];
        int   s1 = g_csr_src[i + 1];
        float w0 = g_csr_w[i];
        float w1 = g_csr_w[i + 1];
        const float* p0 = H + (size_t)s0 * FEAT + lane * VW;
        const float* p1 = H + (size_t)s1 * FEAT + lane * VW;
        if constexpr (VW == 4) {
            float4 v0 = *(const float4*)p0;
            float4 v1 = *(const float4*)p1;
            acc[0] += v0.x * w0 + v1.x * w1;
            acc[1] += v0.y * w0 + v1.y * w1;
            acc[2] += v0.z * w0 + v1.z * w1;
            acc[3] += v0.w * w0 + v1.w * w1;
        } else {
            float2 v0 = *(const float2*)p0;
            float2 v1 = *(const float2*)p1;
            acc[0] += v0.x * w0 + v1.x * w1;
            acc[1] += v0.y * w0 + v1.y * w1;
        }
    }
    if (i < end) {
        int   s0 = g_csr_src[i];
        float w0 = g_csr_w[i];
        const float* p0 = H + (size_t)s0 * FEAT + lane * VW;
        if constexpr (VW == 4) {
            float4 v0 = *(const float4*)p0;
            acc[0] += v0.x * w0; acc[1] += v0.y * w0;
            acc[2] += v0.z * w0; acc[3] += v0.w * w0;
        } else {
            float2 v0 = *(const float2*)p0;
            acc[0] += v0.x * w0; acc[1] += v0.y * w0;
        }
    }

    float* op = Out + (size_t)node * FEAT + lane * VW;
    if constexpr (VW == 4)
        *(float4*)op = make_float4(acc[0], acc[1], acc[2], acc[3]);
    else
        *(float2*)op = make_float2(acc[0], acc[1]);
}

// ---------------- decode: out[e] = dot(z[a]+b2, z[b]+b2) over 64 dims --------
__global__ void decode_kernel(const int* __restrict__ ea,
                              const int* __restrict__ eb,
                              const float* __restrict__ b2,
                              float* __restrict__ out, int ne) {
    long long t = (long long)blockIdx.x * blockDim.x + threadIdx.x;
    int e = (int)(t >> 5);
    int lane = (int)(t & 31);
    if (e >= ne) return;
    int a = ea[e];
    int b = eb[e];
    float2 bb = *(const float2*)(b2 + lane * 2);
    float2 va = *(const float2*)(g_z + (size_t)a * 64 + lane * 2);
    float2 vb = *(const float2*)(g_z + (size_t)b * 64 + lane * 2);
    va.x += bb.x; va.y += bb.y;
    vb.x += bb.x; vb.y += bb.y;
    float p = va.x * vb.x + va.y * vb.y;
#pragma unroll
    for (int o = 16; o > 0; o >>= 1) p += __shfl_down_sync(0xffffffffu, p, o);
    if (lane == 0) out[e] = p;
}

// ---------------- host launch ------------------------------------------------
static inline int cdiv_ll(long long a, int b) { return (int)((a + b - 1) / b); }

extern "C" void kernel_launch(void* const* d_in, const int* in_sizes, int n_in,
                              void* d_out, int out_size) {
    const float* x   = (const float*)d_in[0];
    const int*   ei  = (const int*)d_in[1];    // [2, E] int32
    const float* ew  = (const float*)d_in[2];
    const int*   eli = (const int*)d_in[3];    // [2, EL] int32
    const float* W1  = (const float*)d_in[4];
    const float* b1  = (const float*)d_in[5];
    const float* W2  = (const float*)d_in[6];
    const float* b2  = (const float*)d_in[7];
    float*       out = (float*)d_out;

    const int N  = in_sizes[0] / IN_C;
    const int E  = in_sizes[1] / 2;
    const int EL = in_sizes[3] / 2;

    const int* src = ei;
    const int* dst = ei + E;
    const int* ea  = eli;
    const int* eb  = eli + EL;

    const int T = 256;
    const int nb = (N + SCAN_BT - 1) / SCAN_BT;

    // CSR build + normalization
    init_kernel<<<cdiv_ll(N, T), T>>>(N);
    deg_cnt_kernel<<<cdiv_ll(E, T), T>>>(dst, ew, E);
    dinv_kernel<<<cdiv_ll(N, T), T>>>(N);
    scan1_kernel<<<nb, SCAN_BT>>>(N);
    scan2_kernel<<<1, 128>>>(nb);
    scan3_kernel<<<nb, SCAN_BT>>>(N);
    fill_kernel<<<cdiv_ll(E, T), T>>>(src, dst, ew, E);

    // layer 1: h1 = x @ W1 ; a1 = gather(h1)
    gemm_kernel<HID_C, 1><<<cdiv_ll(N, 64), 256>>>(x, W1, nullptr, N);
    gather_kernel<HID_C, 1><<<cdiv_ll((long long)N * 32, T), T>>>(N);

    // layer 2: h2 = relu(a1+b1) @ W2 ; z = gather(h2)
    gemm_kernel<OUT_C, 2><<<cdiv_ll(N, 64), 256>>>(x, W2, b1, N);
    gather_kernel<OUT_C, 2><<<cdiv_ll((long long)N * 32, T), T>>>(N);

    // decode (b2 fused)
    decode_kernel<<<cdiv_ll((long long)EL * 32, T), T>>>(ea, eb, b2, out, EL);
}

// round 7
// speedup vs baseline: 1.5378x; 1.0019x over previous
#include <cuda_runtime.h>
#include <cuda_bf16.h>
#include <stdint.h>

// ---------------- problem constants (shapes fixed by the dataset) -----------
#define MAXN 100000
#define MAXE 1600000
#define IN_C 128
#define HID_C 128
#define OUT_C 64
#define SCAN_BT 1024

// ---------------- device scratch (no allocs; referenced directly) -----------
__device__ __align__(16) float g_deg [MAXN];
__device__ __align__(16) float g_dinv[MAXN];
__device__ __align__(16) int   g_cnt [MAXN];
__device__ __align__(16) int   g_cur [MAXN];
__device__ __align__(16) int   g_off [MAXN + 1];
__device__ __align__(16) int   g_bsum[128];
__device__ __align__(16) int2  g_csr [MAXE];          // (src, w-as-bits)
__device__ __align__(16) float g_h1[(size_t)MAXN * HID_C];
__device__ __align__(16) float g_a1[(size_t)MAXN * HID_C];
__device__ __align__(16) float g_h2[(size_t)MAXN * OUT_C];
__device__ __align__(16) float g_z [(size_t)MAXN * OUT_C];

// ---------------- degree + in-edge counting ---------------------------------
__global__ void init_kernel(int n) {
    int i = blockIdx.x * blockDim.x + threadIdx.x;
    if (i < n) { g_deg[i] = 1.0f; g_cnt[i] = 0; }
}

__global__ void deg_cnt_kernel(const int* __restrict__ dst,
                               const float* __restrict__ ew, int ne) {
    int e = blockIdx.x * blockDim.x + threadIdx.x;
    if (e < ne) {
        int d = dst[e];
        atomicAdd(&g_deg[d], ew[e]);
        atomicAdd(&g_cnt[d], 1);
    }
}

__global__ void dinv_kernel(int n) {
    int i = blockIdx.x * blockDim.x + threadIdx.x;
    if (i < n) {
        float d = g_deg[i];
        g_dinv[i] = (d > 0.0f) ? rsqrtf(d) : 0.0f;
    }
}

// ---------------- two-level coalesced scan of g_cnt -> g_off ----------------
__global__ void scan1_kernel(int n) {
    __shared__ int wsum[32];
    int tid = threadIdx.x;
    int i = blockIdx.x * SCAN_BT + tid;
    int v = (i < n) ? g_cnt[i] : 0;
    int s = v;
#pragma unroll
    for (int o = 16; o > 0; o >>= 1) s += __shfl_down_sync(0xffffffffu, s, o);
    if ((tid & 31) == 0) wsum[tid >> 5] = s;
    __syncthreads();
    if (tid < 32) {
        int t = wsum[tid];
#pragma unroll
        for (int o = 16; o > 0; o >>= 1) t += __shfl_down_sync(0xffffffffu, t, o);
        if (tid == 0) g_bsum[blockIdx.x] = t;
    }
}

__global__ void scan2_kernel(int nb) {
    __shared__ int sh[128];
    int tid = threadIdx.x;
    int v = (tid < nb) ? g_bsum[tid] : 0;
    sh[tid] = v;
    __syncthreads();
#pragma unroll
    for (int o = 1; o < 128; o <<= 1) {
        int y = 0;
        if (tid >= o) y = sh[tid - o];
        __syncthreads();
        if (tid >= o) sh[tid] += y;
        __syncthreads();
    }
    if (tid < nb) g_bsum[tid] = sh[tid] - v;   // exclusive
}

__global__ void scan3_kernel(int n) {
    __shared__ int wpre[32];
    int tid = threadIdx.x;
    int lane = tid & 31;
    int wid = tid >> 5;
    int i = blockIdx.x * SCAN_BT + tid;
    int v = (i < n) ? g_cnt[i] : 0;
    int x = v;
#pragma unroll
    for (int o = 1; o < 32; o <<= 1) {
        int y = __shfl_up_sync(0xffffffffu, x, o);
        if (lane >= o) x += y;
    }
    if (lane == 31) wpre[wid] = x;
    __syncthreads();
    if (wid == 0) {
        int t = wpre[lane];
        int tv = t;
#pragma unroll
        for (int o = 1; o < 32; o <<= 1) {
            int y = __shfl_up_sync(0xffffffffu, tv, o);
            if (lane >= o) tv += y;
        }
        wpre[lane] = tv - t;
    }
    __syncthreads();
    int bpre = g_bsum[blockIdx.x];
    int excl = bpre + wpre[wid] + (x - v);
    if (i < n) {
        g_off[i] = excl;
        g_cur[i] = excl;
        if (i == n - 1) g_off[n] = excl + v;
    }
}

// fill CSR: (src, w) pairs grouped by dst
__global__ void fill_kernel(const int* __restrict__ src,
                            const int* __restrict__ dst,
                            const float* __restrict__ ew, int ne) {
    int e = blockIdx.x * blockDim.x + threadIdx.x;
    if (e >= ne) return;
    int s = src[e];
    int d = dst[e];
    int slot = atomicAdd(&g_cur[d], 1);
    float w = g_dinv[s] * ew[e] * g_dinv[d];
    g_csr[slot] = make_int2(s, __float_as_int(w));
}

// ---------------- tiled FP32 GEMM -------------------------------------------
// LAYER 1: A = X (arg),         C = g_h1
// LAYER 2: A = relu(g_a1 + b1), C = g_h2
template<int NOUT, int LAYER>
__global__ void gemm_kernel(const float* __restrict__ X,
                            const float* __restrict__ W,
                            const float* __restrict__ bias_in,
                            int nrows) {
    const float* __restrict__ A = (LAYER == 1) ? X : (const float*)g_a1;
    float* __restrict__ C = (LAYER == 1) ? g_h1 : g_h2;

    constexpr int CPT = NOUT / 16;
    __shared__ float As[64][33];
    __shared__ float Ws[32 * NOUT];

    int tid = threadIdx.x;
    int tx = tid & 15, ty = tid >> 4;
    int row0 = blockIdx.x * 64;

    float acc[4][CPT];
#pragma unroll
    for (int i = 0; i < 4; i++)
#pragma unroll
        for (int j = 0; j < CPT; j++) acc[i][j] = 0.0f;

    for (int k0 = 0; k0 < 128; k0 += 32) {
#pragma unroll
        for (int i = 0; i < 2; i++) {
            int idx = tid + i * 256;
            int r  = idx >> 3;
            int cs = (idx & 7) * 4;
            float4 v = make_float4(0.f, 0.f, 0.f, 0.f);
            int row = row0 + r;
            if (row < nrows) {
                v = *(const float4*)(A + (size_t)row * 128 + k0 + cs);
                if (LAYER == 2) {
                    float4 b = *(const float4*)(bias_in + k0 + cs);
                    v.x = fmaxf(v.x + b.x, 0.0f);
                    v.y = fmaxf(v.y + b.y, 0.0f);
                    v.z = fmaxf(v.z + b.z, 0.0f);
                    v.w = fmaxf(v.w + b.w, 0.0f);
                }
            }
            As[r][cs + 0] = v.x; As[r][cs + 1] = v.y;
            As[r][cs + 2] = v.z; As[r][cs + 3] = v.w;
        }
        constexpr int WV = (32 * NOUT) / 4 / 256;
        const float4* Wg = (const float4*)(W + k0 * NOUT);
        float4* Wsv = (float4*)Ws;
#pragma unroll
        for (int i = 0; i < WV; i++) Wsv[tid + i * 256] = Wg[tid + i * 256];
        __syncthreads();

#pragma unroll
        for (int k = 0; k < 32; k++) {
            float a0 = As[ty * 4 + 0][k];
            float a1v = As[ty * 4 + 1][k];
            float a2 = As[ty * 4 + 2][k];
            float a3 = As[ty * 4 + 3][k];
            const float* wrow = &Ws[k * NOUT + tx * CPT];
#pragma unroll
            for (int j = 0; j < CPT; j++) {
                float b = wrow[j];
                acc[0][j] += a0 * b;
                acc[1][j] += a1v * b;
                acc[2][j] += a2 * b;
                acc[3][j] += a3 * b;
            }
        }
        __syncthreads();
    }

#pragma unroll
    for (int i = 0; i < 4; i++) {
        int row = row0 + ty * 4 + i;
        if (row < nrows) {
            float* cp = C + (size_t)row * NOUT + tx * CPT;
#pragma unroll
            for (int j = 0; j < CPT; j += 4)
                *(float4*)(cp + j) = make_float4(acc[i][j], acc[i][j + 1],
                                                 acc[i][j + 2], acc[i][j + 3]);
        }
    }
}

// ---------------- CSR gather aggregation: warp per dst node ------------------
// Out[n] = H[n]*dinv[n]^2 + sum_{in-edges e} w_e * H[src_e]
template<int FEAT, int LAYER>
__global__ void gather_kernel(int n) {
    const float* __restrict__ H = (LAYER == 1) ? g_h1 : g_h2;
    float* __restrict__ Out = (LAYER == 1) ? g_a1 : g_z;
    constexpr int VW = FEAT / 32;            // floats per lane (4 or 2)

    int t = blockIdx.x * blockDim.x + threadIdx.x;
    int node = t >> 5;
    int lane = t & 31;
    if (node >= n) return;

    float di = g_dinv[node];
    float sc = di * di;

    float acc[VW];
    {
        const float* hp = H + (size_t)node * FEAT + lane * VW;
        if constexpr (VW == 4) {
            float4 f = *(const float4*)hp;
            acc[0] = f.x * sc; acc[1] = f.y * sc; acc[2] = f.z * sc; acc[3] = f.w * sc;
        } else {
            float2 f = *(const float2*)hp;
            acc[0] = f.x * sc; acc[1] = f.y * sc;
        }
    }

    int i   = g_off[node];
    int end = g_off[node + 1];

    for (; i + 4 <= end; i += 4) {
        int2 c0 = g_csr[i];
        int2 c1 = g_csr[i + 1];
        int2 c2 = g_csr[i + 2];
        int2 c3 = g_csr[i + 3];
        const float* p0 = H + (size_t)c0.x * FEAT + lane * VW;
        const float* p1 = H + (size_t)c1.x * FEAT + lane * VW;
        const float* p2 = H + (size_t)c2.x * FEAT + lane * VW;
        const float* p3 = H + (size_t)c3.x * FEAT + lane * VW;
        float w0 = __int_as_float(c0.y), w1 = __int_as_float(c1.y);
        float w2 = __int_as_float(c2.y), w3 = __int_as_float(c3.y);
        if constexpr (VW == 4) {
            float4 v0 = *(const float4*)p0;
            float4 v1 = *(const float4*)p1;
            float4 v2 = *(const float4*)p2;
            float4 v3 = *(const float4*)p3;
            acc[0] += v0.x * w0 + v1.x * w1 + v2.x * w2 + v3.x * w3;
            acc[1] += v0.y * w0 + v1.y * w1 + v2.y * w2 + v3.y * w3;
            acc[2] += v0.z * w0 + v1.z * w1 + v2.z * w2 + v3.z * w3;
            acc[3] += v0.w * w0 + v1.w * w1 + v2.w * w2 + v3.w * w3;
        } else {
            float2 v0 = *(const float2*)p0;
            float2 v1 = *(const float2*)p1;
            float2 v2 = *(const float2*)p2;
            float2 v3 = *(const float2*)p3;
            acc[0] += v0.x * w0 + v1.x * w1 + v2.x * w2 + v3.x * w3;
            acc[1] += v0.y * w0 + v1.y * w1 + v2.y * w2 + v3.y * w3;
        }
    }
    for (; i < end; i++) {
        int2 c = g_csr[i];
        float w = __int_as_float(c.y);
        const float* p = H + (size_t)c.x * FEAT + lane * VW;
        if constexpr (VW == 4) {
            float4 v = *(const float4*)p;
            acc[0] += v.x * w; acc[1] += v.y * w;
            acc[2] += v.z * w; acc[3] += v.w * w;
        } else {
            float2 v = *(const float2*)p;
            acc[0] += v.x * w; acc[1] += v.y * w;
        }
    }

    float* op = Out + (size_t)node * FEAT + lane * VW;
    if constexpr (VW == 4)
        *(float4*)op = make_float4(acc[0], acc[1], acc[2], acc[3]);
    else
        *(float2*)op = make_float2(acc[0], acc[1]);
}

// ---------------- decode: out[e] = dot(z[a]+b2, z[b]+b2) over 64 dims --------
__global__ void decode_kernel(const int* __restrict__ ea,
                              const int* __restrict__ eb,
                              const float* __restrict__ b2,
                              float* __restrict__ out, int ne) {
    long long t = (long long)blockIdx.x * blockDim.x + threadIdx.x;
    int e = (int)(t >> 5);
    int lane = (int)(t & 31);
    if (e >= ne) return;
    int a = ea[e];
    int b = eb[e];
    float2 bb = *(const float2*)(b2 + lane * 2);
    float2 va = *(const float2*)(g_z + (size_t)a * 64 + lane * 2);
    float2 vb = *(const float2*)(g_z + (size_t)b * 64 + lane * 2);
    va.x += bb.x; va.y += bb.y;
    vb.x += bb.x; vb.y += bb.y;
    float p = va.x * vb.x + va.y * vb.y;
#pragma unroll
    for (int o = 16; o > 0; o >>= 1) p += __shfl_down_sync(0xffffffffu, p, o);
    if (lane == 0) out[e] = p;
}

// ---------------- host launch ------------------------------------------------
static inline int cdiv_ll(long long a, int b) { return (int)((a + b - 1) / b); }

extern "C" void kernel_launch(void* const* d_in, const int* in_sizes, int n_in,
                              void* d_out, int out_size) {
    const float* x   = (const float*)d_in[0];
    const int*   ei  = (const int*)d_in[1];    // [2, E] int32
    const float* ew  = (const float*)d_in[2];
    const int*   eli = (const int*)d_in[3];    // [2, EL] int32
    const float* W1  = (const float*)d_in[4];
    const float* b1  = (const float*)d_in[5];
    const float* W2  = (const float*)d_in[6];
    const float* b2  = (const float*)d_in[7];
    float*       out = (float*)d_out;

    const int N  = in_sizes[0] / IN_C;
    const int E  = in_sizes[1] / 2;
    const int EL = in_sizes[3] / 2;

    const int* src = ei;
    const int* dst = ei + E;
    const int* ea  = eli;
    const int* eb  = eli + EL;

    const int T = 256;
    const int nb = (N + SCAN_BT - 1) / SCAN_BT;

    // one-time side-stream + events (no device memory involved; created on the
    // first, uncaptured call and reused by the capture call)
    static cudaStream_t s2 = nullptr;
    static cudaEvent_t evA = nullptr, evB = nullptr;
    if (s2 == nullptr) {
        cudaStreamCreateWithFlags(&s2, cudaStreamNonBlocking);
        cudaEventCreateWithFlags(&evA, cudaEventDisableTiming);
        cudaEventCreateWithFlags(&evB, cudaEventDisableTiming);
    }

    // fork: gemm1 (independent of graph structure) runs on s2
    cudaEventRecord(evA, 0);
    cudaStreamWaitEvent(s2, evA, 0);
    gemm_kernel<HID_C, 1><<<cdiv_ll(N, 64), 256, 0, s2>>>(x, W1, nullptr, N);
    cudaEventRecord(evB, s2);

    // CSR build + normalization on the main (capture) stream
    init_kernel<<<cdiv_ll(N, T), T>>>(N);
    deg_cnt_kernel<<<cdiv_ll(E, T), T>>>(dst, ew, E);
    dinv_kernel<<<cdiv_ll(N, T), T>>>(N);
    scan1_kernel<<<nb, SCAN_BT>>>(N);
    scan2_kernel<<<1, 128>>>(nb);
    scan3_kernel<<<nb, SCAN_BT>>>(N);
    fill_kernel<<<cdiv_ll(E, T), T>>>(src, dst, ew, E);

    // join: gather1 needs both h1 (s2) and CSR (main)
    cudaStreamWaitEvent(0, evB, 0);
    gather_kernel<HID_C, 1><<<cdiv_ll((long long)N * 32, T), T>>>(N);

    // layer 2 + decode on main stream
    gemm_kernel<OUT_C, 2><<<cdiv_ll(N, 64), 256>>>(x, W2, b1, N);
    gather_kernel<OUT_C, 2><<<cdiv_ll((long long)N * 32, T), T>>>(N);
    decode_kernel<<<cdiv_ll((long long)EL * 32, T), T>>>(ea, eb, b2, out, EL);
}